// round 2
// baseline (speedup 1.0000x reference)
#include <cuda_runtime.h>
#include <cstdint>

// Problem shape: x [8,4096,512] f32, codebook [4096,512] f32
//   N = 32768 tokens, M = 4096 codes, D = 512
// Outputs concatenated in d_out (f32): q_st [N*D], commitment_loss [N], cb_n [M*D]

#define D_DIM 512
#define EPSN 1e-12f

// ---------------- device scratch (no allocations allowed) ----------------
__device__ float              g_cbn[4096 * 512];     // normalized codebook
__device__ float              g_invnx[32768];        // 1/max(||x_n||, eps)
__device__ unsigned long long g_best[32768];         // packed (flipped sim || ~idx)

// monotone float->uint mapping (order-preserving)
__device__ __forceinline__ unsigned flip_f(unsigned fb) {
    return (fb & 0x80000000u) ? ~fb : (fb | 0x80000000u);
}
__device__ __forceinline__ unsigned unflip_f(unsigned u) {
    return (u & 0x80000000u) ? (u & 0x7FFFFFFFu) : ~u;
}
__device__ __forceinline__ unsigned long long make_key(unsigned fbits, int idx) {
    return (((unsigned long long)flip_f(fbits)) << 32) |
           (unsigned long long)(0xFFFFFFFFu - (unsigned)idx);
}

// ---------------- kernel 1: normalize codebook rows ----------------
__global__ void norm_cb_kernel(const float* __restrict__ cb,
                               float* __restrict__ out_cb, int M) {
    int row = blockIdx.x;
    int tid = threadIdx.x;   // 128 threads, 4 floats each
    const float4 v = *(const float4*)(cb + (size_t)row * D_DIM + tid * 4);
    float s = v.x * v.x + v.y * v.y + v.z * v.z + v.w * v.w;
    #pragma unroll
    for (int off = 16; off > 0; off >>= 1)
        s += __shfl_down_sync(0xffffffffu, s, off);
    __shared__ float ws[4];
    __shared__ float sinv;
    if ((tid & 31) == 0) ws[tid >> 5] = s;
    __syncthreads();
    if (tid == 0) {
        float tot = ws[0] + ws[1] + ws[2] + ws[3];
        sinv = 1.0f / fmaxf(sqrtf(tot), EPSN);
    }
    __syncthreads();
    float inv = sinv;
    float4 o;
    o.x = v.x * inv; o.y = v.y * inv; o.z = v.z * inv; o.w = v.w * inv;
    *(float4*)(g_cbn + (size_t)row * D_DIM + tid * 4) = o;
    if (out_cb)
        *(float4*)(out_cb + (size_t)row * D_DIM + tid * 4) = o;
}

// ---------------- kernel 2: x row inverse norms (+ init best) ----------------
__global__ void norm_x_kernel(const float* __restrict__ x, int N) {
    int row = blockIdx.x;
    int tid = threadIdx.x;
    const float4 v = *(const float4*)(x + (size_t)row * D_DIM + tid * 4);
    float s = v.x * v.x + v.y * v.y + v.z * v.z + v.w * v.w;
    #pragma unroll
    for (int off = 16; off > 0; off >>= 1)
        s += __shfl_down_sync(0xffffffffu, s, off);
    __shared__ float ws[4];
    if ((tid & 31) == 0) ws[tid >> 5] = s;
    __syncthreads();
    if (tid == 0) {
        float tot = ws[0] + ws[1] + ws[2] + ws[3];
        g_invnx[row] = 1.0f / fmaxf(sqrtf(tot), EPSN);
        g_best[row] = 0ull;
    }
}

// ---------------- kernel 3: fp32 GEMM (x . cb_n^T) + fused argmax ----------------
// 128x128 tile, TK=16, 256 threads, 8x8 microtile, packed f32x2 FMA,
// single-stage register prefetch of the next global tile.
#define TM 128
#define TN 128
#define TK 16

__global__ __launch_bounds__(256, 2)
void gemm_argmax_kernel(const float* __restrict__ A,   // [N, 512] raw x
                        const float* __restrict__ B,   // [M, 512] normalized cb
                        unsigned long long* __restrict__ best,
                        int K) {
    __shared__ float As[TK][TM + 4];   // stride 132 floats = 528B (16B-mult)
    __shared__ float Bs[TK][TN + 4];   // stride 132: LDS.128-friendly

    const int tid = threadIdx.x;
    const int tx = tid & 15;          // code-dim thread coord
    const int ty = tid >> 4;          // token-dim thread coord
    const int nBase = blockIdx.y * TM;
    const int mBase = blockIdx.x * TN;
    const int rowBase = ty * 8;
    const int colBase = tx * 8;

    // per-thread gmem load coords (2 float4 per operand per tile)
    const int ldn0 = tid >> 2,        ldk0 = (tid & 3) * 4;
    const int ldn1 = (tid + 256) >> 2, ldk1 = ((tid + 256) & 3) * 4;

    const float* Arow0 = A + (size_t)(nBase + ldn0) * K + ldk0;
    const float* Arow1 = A + (size_t)(nBase + ldn1) * K + ldk1;
    const float* Brow0 = B + (size_t)(mBase + ldn0) * K + ldk0;
    const float* Brow1 = B + (size_t)(mBase + ldn1) * K + ldk1;

    unsigned long long acc[8][4];
    #pragma unroll
    for (int i = 0; i < 8; i++)
        #pragma unroll
        for (int p = 0; p < 4; p++) acc[i][p] = 0ull;   // (0.0f, 0.0f)

    // preload tile 0
    float4 rA0 = *(const float4*)(Arow0);
    float4 rA1 = *(const float4*)(Arow1);
    float4 rB0 = *(const float4*)(Brow0);
    float4 rB1 = *(const float4*)(Brow1);

    for (int k0 = 0; k0 < K; k0 += TK) {
        // ---- store prefetched regs into SMEM (transposed) ----
        {
            int n = ldn0, kq = ldk0 >> 2;
            As[kq * 4 + 0][n] = rA0.x; As[kq * 4 + 1][n] = rA0.y;
            As[kq * 4 + 2][n] = rA0.z; As[kq * 4 + 3][n] = rA0.w;
            Bs[kq * 4 + 0][n] = rB0.x; Bs[kq * 4 + 1][n] = rB0.y;
            Bs[kq * 4 + 2][n] = rB0.z; Bs[kq * 4 + 3][n] = rB0.w;
            n = ldn1; kq = ldk1 >> 2;
            As[kq * 4 + 0][n] = rA1.x; As[kq * 4 + 1][n] = rA1.y;
            As[kq * 4 + 2][n] = rA1.z; As[kq * 4 + 3][n] = rA1.w;
            Bs[kq * 4 + 0][n] = rB1.x; Bs[kq * 4 + 1][n] = rB1.y;
            Bs[kq * 4 + 2][n] = rB1.z; Bs[kq * 4 + 3][n] = rB1.w;
        }
        __syncthreads();

        // ---- issue next tile's global loads (overlap with compute) ----
        if (k0 + TK < K) {
            rA0 = *(const float4*)(Arow0 + k0 + TK);
            rA1 = *(const float4*)(Arow1 + k0 + TK);
            rB0 = *(const float4*)(Brow0 + k0 + TK);
            rB1 = *(const float4*)(Brow1 + k0 + TK);
        }

        #pragma unroll
        for (int k = 0; k < TK; k++) {
            float a[8];
            *(float4*)(a)     = *(const float4*)(&As[k][rowBase]);
            *(float4*)(a + 4) = *(const float4*)(&As[k][rowBase + 4]);
            unsigned long long b[4];
            {
                ulonglong2 b01 = *(const ulonglong2*)(&Bs[k][colBase]);
                ulonglong2 b23 = *(const ulonglong2*)(&Bs[k][colBase + 4]);
                b[0] = b01.x; b[1] = b01.y; b[2] = b23.x; b[3] = b23.y;
            }
            #pragma unroll
            for (int i = 0; i < 8; i++) {
                unsigned long long pa;
                asm("mov.b64 %0, {%1, %1};" : "=l"(pa) : "r"(__float_as_uint(a[i])));
                #pragma unroll
                for (int p = 0; p < 4; p++) {
                    asm("fma.rn.f32x2 %0, %1, %2, %3;"
                        : "=l"(acc[i][p])
                        : "l"(pa), "l"(b[p]), "l"(acc[i][p]));
                }
            }
        }
        __syncthreads();
    }

    // ---- fused argmax epilogue ----
    #pragma unroll
    for (int i = 0; i < 8; i++) {
        unsigned long long bk = 0ull;
        #pragma unroll
        for (int p = 0; p < 4; p++) {
            unsigned lo = (unsigned)(acc[i][p] & 0xFFFFFFFFull);
            unsigned hi = (unsigned)(acc[i][p] >> 32);
            int c0 = mBase + colBase + 2 * p;
            unsigned long long k0p = make_key(lo, c0);
            unsigned long long k1p = make_key(hi, c0 + 1);
            if (k0p > bk) bk = k0p;
            if (k1p > bk) bk = k1p;
        }
        // reduce across the 16 code-dim lanes (half-warp segment = one ty)
        #pragma unroll
        for (int off = 8; off > 0; off >>= 1) {
            unsigned long long o = __shfl_down_sync(0xffffffffu, bk, off, 16);
            if (o > bk) bk = o;
        }
        if (tx == 0)
            atomicMax(&best[nBase + rowBase + i], bk);
    }
}

// ---------------- kernel 4: finalize (gather q_st + loss) ----------------
__global__ void finalize_kernel(float* __restrict__ q_out,
                                float* __restrict__ loss_out, int N) {
    int n = blockIdx.x;
    int tid = threadIdx.x;   // 128 threads, one float4 each
    unsigned long long pk = g_best[n];
    unsigned idx = 0xFFFFFFFFu - (unsigned)(pk & 0xFFFFFFFFull);
    float dot = __uint_as_float(unflip_f((unsigned)(pk >> 32)));
    float4 v = *(const float4*)(g_cbn + (size_t)idx * D_DIM + tid * 4);
    *(float4*)(q_out + (size_t)n * D_DIM + tid * 4) = v;
    if (tid == 0 && loss_out)
        loss_out[n] = 1.0f - dot * g_invnx[n];
}

// ---------------- host launch ----------------
extern "C" void kernel_launch(void* const* d_in, const int* in_sizes, int n_in,
                              void* d_out, int out_size) {
    const float* x  = (const float*)d_in[0];
    const float* cb = (const float*)d_in[1];
    const int N = in_sizes[0] / D_DIM;   // 32768
    const int M = in_sizes[1] / D_DIM;   // 4096

    float* out = (float*)d_out;
    float* q_out = out;
    float* loss_out = nullptr;
    float* cb_out = nullptr;
    long long need_full = (long long)N * D_DIM + N + (long long)M * D_DIM;
    if ((long long)out_size >= need_full) {
        loss_out = out + (size_t)N * D_DIM;
        cb_out = loss_out + N;
    } else if ((long long)out_size >= (long long)N * D_DIM + N) {
        loss_out = out + (size_t)N * D_DIM;
    }

    // CRITICAL: device-symbol addresses must come from cudaGetSymbolAddress;
    // naming a __device__ symbol in host code passes the host shadow (and on
    // GB300 ATS that READS HOST MEMORY silently instead of faulting).
    float* cbn_p = nullptr;
    cudaGetSymbolAddress((void**)&cbn_p, g_cbn);
    unsigned long long* bestp = nullptr;
    cudaGetSymbolAddress((void**)&bestp, g_best);

    norm_cb_kernel<<<M, 128>>>(cb, cb_out, M);
    norm_x_kernel<<<N, 128>>>(x, N);

    dim3 grid(M / TN, N / TM);
    gemm_argmax_kernel<<<grid, 256>>>(x, cbn_p, bestp, D_DIM);

    finalize_kernel<<<N, 128>>>(q_out, loss_out, N);
}